// round 16
// baseline (speedup 1.0000x reference)
#include <cuda_runtime.h>
#include <math.h>

#define N_ 8
#define C_ 512
#define H_ 64
#define W_ 64

typedef unsigned long long ull;

__device__ __forceinline__ ull pack2(float lo, float hi) {
    ull r; asm("mov.b64 %0, {%1, %2};" : "=l"(r) : "f"(lo), "f"(hi)); return r;
}
__device__ __forceinline__ void unpack2(ull v, float& lo, float& hi) {
    asm("mov.b64 {%0, %1}, %2;" : "=f"(lo), "=f"(hi) : "l"(v));
}
__device__ __forceinline__ ull fma2(ull a, ull b, ull c) {
    ull d; asm("fma.rn.f32x2 %0, %1, %2, %3;" : "=l"(d) : "l"(a), "l"(b), "l"(c)); return d;
}
__device__ __forceinline__ ull mul2(ull a, ull b) {
    ull d; asm("mul.rn.f32x2 %0, %1, %2;" : "=l"(d) : "l"(a), "l"(b)); return d;
}
__device__ __forceinline__ float tanh_ap(float x) {
    float r; asm("tanh.approx.f32 %0, %1;" : "=f"(r) : "f"(x)); return r;
}
__device__ __forceinline__ unsigned tf32_of(float f) {
    unsigned u; asm("cvt.rna.tf32.f32 %0, %1;" : "=r"(u) : "f"(f)); return u;
}
// tanh-form GELU on an f32x2 pair
__device__ __forceinline__ ull gelu2(ull y, ull C1, ull C0, ull HF) {
    ull x2 = mul2(y, y);
    ull u  = mul2(y, fma2(C1, x2, C0));
    float u0, u1;
    unpack2(u, u0, u1);
    ull t2 = pack2(tanh_ap(u0), tanh_ap(u1));
    ull r  = fma2(t2, HF, HF);
    return mul2(y, r);
}
// m16n8k8 tf32 MMA, D += A*B
__device__ __forceinline__ void mma_tf32(float* d, const unsigned* a,
                                         unsigned b0, unsigned b1) {
    asm volatile(
        "mma.sync.aligned.m16n8k8.row.col.f32.tf32.tf32.f32 "
        "{%0,%1,%2,%3},{%4,%5,%6,%7},{%8,%9},{%0,%1,%2,%3};"
        : "+f"(d[0]), "+f"(d[1]), "+f"(d[2]), "+f"(d[3])
        : "r"(a[0]), "r"(a[1]), "r"(a[2]), "r"(a[3]), "r"(b0), "r"(b1));
}

// Shared memory (floats), per CTA of 512 threads covering 32 pixels:
//   region0 (18432): x1 [512 rows][36] A-D (tf32 bits after C);
//                    after D: partials [16 warps][32 o, stride 34] = 17408;
//                    stage [512][33] E/F
//   offsP   (8192):  phase0-A: dwws [0:6144]; A/B: psum/psq [6144:7200]
//                    C-D: half of off_w^T as tf32 scalars, swizzled
//                         wsm[c*32 + (o ^ ((c&3)<<3))], 256x32 = 8192
//                    E0/E: spw 4x512 ull [0:4096] + spo int4 [4096:6144]
//   mu,rs   : 64
// total = 26688 floats = 106752 B  -> 2 CTAs/SM
#define SMEM_FLOATS (18432 + 8192 + 64)

__global__ __launch_bounds__(512, 2)
void das_fused_kernel(const float* __restrict__ in0,   // input_first NCHW
                      const float* __restrict__ inL,   // input_last  NHWC
                      const float* __restrict__ dw_w,  // [C,1,3,3]
                      const float* __restrict__ dw_b,  // [C]
                      const float* __restrict__ ln_g,  // [C]
                      const float* __restrict__ ln_b,  // [C]
                      const float* __restrict__ off_w, // [2G, C]
                      const float* __restrict__ off_b, // [2G]
                      float* __restrict__ out)         // NCHW
{
    extern __shared__ float sm[];
    float* x1    = sm;                 // stride 36 rows (A-D)
    float* stage = sm;                 // stride 33 rows (E-F)
    float* parts = sm;                 // [0:17408] after D (x1 dead)
    float* offsP = sm + 18432;         // 8192
    float* dwws  = offsP;              // [0:6144] staged dw weights
    float* psum  = offsP + 6144;       // 16 x 33 = 528
    float* psq   = offsP + 6672;       // 16 x 33 = 528
    unsigned* wsu = (unsigned*)offsP;  // [0:8192] staged tf32 weights (C-D)
    ull*   spw   = (ull*)offsP;        // [0:4096] (E0/E)
    int4*  spo   = (int4*)(offsP + 4096);  // [4096:6144] tap offsets
    float* mu    = sm + 18432 + 8192;  // 32
    float* rs    = mu + 32;            // 32

    const int t     = threadIdx.x;
    const int half  = blockIdx.x;      // 0 or 1
    const int h     = blockIdx.y;
    const int n     = blockIdx.z;
    const int wbase = half * 32;

    const int w4   = t & 7;            // w-quad within the 32 pixels
    const int cgrp = t >> 3;           // 0..63, 8 channels each
    const int lane = t & 31;

    // ======== Phase 0: stage dw_w (9-stride) into dwws (12-stride) ==========
    {
        const float4* s4 = (const float4*)dw_w;   // 4608 floats = 1152 float4
        #pragma unroll
        for (int k = 0; k < 3; ++k) {
            int idx = t + k * 512;
            if (idx < 1152) {
                float4 v = __ldg(s4 + idx);
                float va[4] = {v.x, v.y, v.z, v.w};
                int j0 = idx * 4;
                #pragma unroll
                for (int e = 0; e < 4; ++e) {
                    int j = j0 + e;
                    int c = (int)(((unsigned)j * 7282u) >> 16);   // j / 9
                    int r = j - c * 9;
                    dwws[c * 12 + r] = va[e];
                }
            }
        }
    }
    __syncthreads();

    // ======== Phase A: depthwise 3x3 conv + bias + LN partials ==============
    float s0 = 0.f, s1 = 0.f, s2 = 0.f, s3 = 0.f;
    float q0 = 0.f, q1 = 0.f, q2 = 0.f, q3 = 0.f;

    const float* in_n = in0 + (size_t)n * C_ * H_ * W_;

    #pragma unroll 4
    for (int i = 0; i < 8; ++i) {
        int c = cgrp * 8 + i;
        const float4* wp4 = (const float4*)(dwws + c * 12);
        float4 wA = wp4[0];
        float4 wB = wp4[1];
        float4 wC = wp4[2];
        const float* cp = in_n + (size_t)c * H_ * W_;
        float b = __ldg(dw_b + c);
        float a0 = b, a1 = b, a2 = b, a3 = b;
        #pragma unroll
        for (int dy = -1; dy <= 1; ++dy) {
            int hy = h + dy;
            if ((unsigned)hy < (unsigned)H_) {          // uniform across block
                const float* r = cp + hy * W_ + wbase + w4 * 4;
                float4 v = *(const float4*)r;
                float lf = __shfl_up_sync(0xffffffffu, v.w, 1, 8);
                if (w4 == 0) lf = (wbase > 0) ? r[-1] : 0.f;
                float rt = __shfl_down_sync(0xffffffffu, v.x, 1, 8);
                if (w4 == 7) rt = (wbase + 32 < W_) ? r[4] : 0.f;
                float k0, k1, k2;
                if (dy == -1)     { k0 = wA.x; k1 = wA.y; k2 = wA.z; }
                else if (dy == 0) { k0 = wA.w; k1 = wB.x; k2 = wB.y; }
                else              { k0 = wB.z; k1 = wB.w; k2 = wC.x; }
                a0 += k0 * lf  + k1 * v.x + k2 * v.y;
                a1 += k0 * v.x + k1 * v.y + k2 * v.z;
                a2 += k0 * v.y + k1 * v.z + k2 * v.w;
                a3 += k0 * v.z + k1 * v.w + k2 * rt;
            }
        }
        s0 += a0; q0 += a0 * a0;
        s1 += a1; q1 += a1 * a1;
        s2 += a2; q2 += a2 * a2;
        s3 += a3; q3 += a3 * a3;
        *(float4*)(x1 + c * 36 + w4 * 4) = make_float4(a0, a1, a2, a3);
    }

    s0 += __shfl_xor_sync(0xffffffffu, s0, 8);
    s0 += __shfl_xor_sync(0xffffffffu, s0, 16);
    s1 += __shfl_xor_sync(0xffffffffu, s1, 8);
    s1 += __shfl_xor_sync(0xffffffffu, s1, 16);
    s2 += __shfl_xor_sync(0xffffffffu, s2, 8);
    s2 += __shfl_xor_sync(0xffffffffu, s2, 16);
    s3 += __shfl_xor_sync(0xffffffffu, s3, 8);
    s3 += __shfl_xor_sync(0xffffffffu, s3, 16);
    q0 += __shfl_xor_sync(0xffffffffu, q0, 8);
    q0 += __shfl_xor_sync(0xffffffffu, q0, 16);
    q1 += __shfl_xor_sync(0xffffffffu, q1, 8);
    q1 += __shfl_xor_sync(0xffffffffu, q1, 16);
    q2 += __shfl_xor_sync(0xffffffffu, q2, 8);
    q2 += __shfl_xor_sync(0xffffffffu, q2, 16);
    q3 += __shfl_xor_sync(0xffffffffu, q3, 8);
    q3 += __shfl_xor_sync(0xffffffffu, q3, 16);
    {
        int warpId = t >> 5;               // 0..15
        if (lane < 8) {
            psum[warpId * 33 + lane * 4 + 0] = s0;
            psum[warpId * 33 + lane * 4 + 1] = s1;
            psum[warpId * 33 + lane * 4 + 2] = s2;
            psum[warpId * 33 + lane * 4 + 3] = s3;
            psq [warpId * 33 + lane * 4 + 0] = q0;
            psq [warpId * 33 + lane * 4 + 1] = q1;
            psq [warpId * 33 + lane * 4 + 2] = q2;
            psq [warpId * 33 + lane * 4 + 3] = q3;
        }
    }
    __syncthreads();

    // ======== Phase B: finish LN statistics, all threads + shfl =============
    {
        int px = t >> 4;      // 0..31
        int j  = t & 15;      // partial index
        float s = psum[j * 33 + px];
        float q = psq [j * 33 + px];
        #pragma unroll
        for (int d = 8; d >= 1; d >>= 1) {
            s += __shfl_xor_sync(0xffffffffu, s, d);
            q += __shfl_xor_sync(0xffffffffu, q, d);
        }
        if (j == 0) {
            float m = s * (1.0f / 512.0f);
            float var = q * (1.0f / 512.0f) - m * m;
            mu[px] = m;
            rs[px] = rsqrtf(var + 1e-6f);
        }
    }
    __syncthreads();

    // ======== Phase C: LN + fast GELU -> tf32; stage weight half 0 ==========
    {
        // stage tf32 off_w^T for c in [0,256): wsu[c*32 + (o ^ ((c&3)<<3))]
        {
            int c  = t >> 1;               // local c
            int ob = (t & 1) * 16;         // 16 o's per thread
            #pragma unroll
            for (int j = 0; j < 16; ++j) {
                int o = ob + j;
                float v = __ldg(off_w + o * 512 + c);
                wsu[c * 32 + (o ^ ((c & 3) << 3))] = tf32_of(v);
            }
        }

        float4 m4 = *(const float4*)(mu + w4 * 4);
        float4 r4 = *(const float4*)(rs + w4 * 4);
        const ull C1 = pack2(0.0356774081f, 0.0356774081f);
        const ull C0 = pack2(0.7978845608f, 0.7978845608f);
        const ull HF = pack2(0.5f, 0.5f);
        ull r2lo = pack2(r4.x, r4.y);
        ull r2hi = pack2(r4.z, r4.w);
        ull mn2lo = pack2(-m4.x, -m4.y);
        ull mn2hi = pack2(-m4.z, -m4.w);
        #pragma unroll
        for (int q = 0; q < 2; ++q) {
            int c0 = cgrp * 8 + q * 4;
            float4 gq = __ldg((const float4*)(ln_g + c0));
            float4 bq = __ldg((const float4*)(ln_b + c0));
            float gga[4] = {gq.x, gq.y, gq.z, gq.w};
            float bba[4] = {bq.x, bq.y, bq.z, bq.w};
            #pragma unroll
            for (int j = 0; j < 4; ++j) {
                int c = c0 + j;
                ull g2 = pack2(gga[j], gga[j]);
                ull b2 = pack2(bba[j], bba[j]);
                ulonglong2 yv = *(const ulonglong2*)(x1 + c * 36 + w4 * 4);
                ull Alo = mul2(r2lo, g2);
                ull Blo = fma2(mn2lo, Alo, b2);
                ull Ahi = mul2(r2hi, g2);
                ull Bhi = fma2(mn2hi, Ahi, b2);
                yv.x = fma2(yv.x, Alo, Blo);
                yv.y = fma2(yv.y, Ahi, Bhi);
                yv.x = gelu2(yv.x, C1, C0, HF);
                yv.y = gelu2(yv.y, C1, C0, HF);
                float f0, f1, f2, f3;
                unpack2(yv.x, f0, f1);
                unpack2(yv.y, f2, f3);
                uint4 st;
                st.x = tf32_of(f0);
                st.y = tf32_of(f1);
                st.z = tf32_of(f2);
                st.w = tf32_of(f3);
                *(uint4*)(x1 + c * 36 + w4 * 4) = st;
            }
        }
    }
    __syncthreads();

    // ======== Phase D: offset projection via m16n8k8 tf32 MMA ===============
    // out[32o x 32w] = W[32 x 512] * X[512 x 32]; 16-way warp k-split,
    // 2 staging passes (weights for c-half in wsu).
    {
        const int wid = t >> 5;        // 0..15, k-slice: c in [32*wid, +32)
        const int g   = lane >> 2;     // groupID
        const int tig = lane & 3;      // thread in group
        const unsigned* x1u = (const unsigned*)x1;
        float acc[2][4][4];
        #pragma unroll
        for (int m = 0; m < 2; ++m)
            #pragma unroll
            for (int nn = 0; nn < 4; ++nn)
                #pragma unroll
                for (int e = 0; e < 4; ++e) acc[m][nn][e] = 0.f;

        #pragma unroll
        for (int pass = 0; pass < 2; ++pass) {
            if (pass == 1) {
                __syncthreads();     // pass-0 weight reads complete
                int c  = t >> 1;
                int ob = (t & 1) * 16;
                #pragma unroll
                for (int j = 0; j < 16; ++j) {
                    int o = ob + j;
                    float v = __ldg(off_w + o * 512 + 256 + c);
                    wsu[c * 32 + (o ^ ((c & 3) << 3))] = tf32_of(v);
                }
                __syncthreads();     // half-1 staged
            }
            #pragma unroll
            for (int ks = 0; ks < 2; ++ks) {
                int cl = wid * 16 + ks * 8;         // local c base (k8 tile)
                int cg = pass * 256 + cl;           // global c base
                int cA0 = cl + tig;
                int cA1 = cl + tig + 4;
                unsigned a[2][4];
                #pragma unroll
                for (int m = 0; m < 2; ++m) {
                    int ob = m * 16;
                    a[m][0] = wsu[cA0 * 32 + ((g + ob)     ^ ((cA0 & 3) << 3))];
                    a[m][1] = wsu[cA0 * 32 + ((g + 8 + ob) ^ ((cA0 & 3) << 3))];
                    a[m][2] = wsu[cA1 * 32 + ((g + ob)     ^ ((cA1 & 3) << 3))];
                    a[m][3] = wsu[cA1 * 32 + ((g + 8 + ob) ^ ((cA1 & 3) << 3))];
                }
                int cB0 = cg + tig;
                int cB1 = cg + tig + 4;
                #pragma unroll
                for (int nn = 0; nn < 4; ++nn) {
                    unsigned b0 = x1u[cB0 * 36 + nn * 8 + g];
                    unsigned b1 = x1u[cB1 * 36 + nn * 8 + g];
                    mma_tf32(acc[0][nn], a[0], b0, b1);
                    mma_tf32(acc[1][nn], a[1], b0, b1);
                }
            }
        }
        __syncthreads();   // all x1 + wsu reads complete; region0 -> parts

        float* pb = parts + wid * 1088;     // o-stride 34
        #pragma unroll
        for (int m = 0; m < 2; ++m) {
            int o0 = g + m * 16;
            #pragma unroll
            for (int nn = 0; nn < 4; ++nn) {
                int wp = nn * 8 + 2 * tig;
                *(float2*)(pb + o0 * 34 + wp) =
                    make_float2(acc[m][nn][0], acc[m][nn][1]);
                *(float2*)(pb + (o0 + 8) * 34 + wp) =
                    make_float2(acc[m][nn][2], acc[m][nn][3]);
            }
        }
    }
    __syncthreads();

    // ======== Phase E0: reduce 16 partials + per-sample bilinear params ======
    {
        const int S = t;            // 0..511
        const int g = S >> 5;
        const int w = S & 31;
        float sx = __ldg(off_b + 2 * g);
        float sy = __ldg(off_b + 2 * g + 1);
        #pragma unroll
        for (int p = 0; p < 16; ++p) {
            sx += parts[p * 1088 + (2 * g) * 34 + w];
            sy += parts[p * 1088 + (2 * g) * 34 + 34 + w];
        }
        float px = (float)(wbase + w) + sx;
        float py = (float)h           + sy;
        float x0f = floorf(px);
        float y0f = floorf(py);
        float fx = px - x0f;
        float fy = py - y0f;
        int x0 = (int)x0f;
        int y0 = (int)y0f;
        float vx0 = (x0f >= 0.f       && x0f <= 63.f)       ? 1.f : 0.f;
        float vx1 = (x0f + 1.f >= 0.f && x0f + 1.f <= 63.f) ? 1.f : 0.f;
        float vy0 = (y0f >= 0.f       && y0f <= 63.f)       ? 1.f : 0.f;
        float vy1 = (y0f + 1.f >= 0.f && y0f + 1.f <= 63.f) ? 1.f : 0.f;
        int xc0 = min(max(x0, 0), 63);
        int xc1 = min(max(x0 + 1, 0), 63);
        int yc0 = min(max(y0, 0), 63);
        int yc1 = min(max(y0 + 1, 0), 63);
        float w00 = (1.f - fx) * (1.f - fy) * vx0 * vy0;
        float w10 = fx * (1.f - fy) * vx1 * vy0;
        float w01 = (1.f - fx) * fy * vx0 * vy1;
        float w11 = fx * fy * vx1 * vy1;
        spw[S +    0] = pack2(w00, w00);
        spw[S +  512] = pack2(w10, w10);
        spw[S + 1024] = pack2(w01, w01);
        spw[S + 1536] = pack2(w11, w11);
        spo[S] = make_int4((yc0 * 64 + xc0) * 512, (yc0 * 64 + xc1) * 512,
                           (yc1 * 64 + xc0) * 512, (yc1 * 64 + xc1) * 512);
    }
    __syncthreads();

    // ======== Phase E: coalesced bilinear gather (8 lanes per sample) =======
    {
        const int wp = t >> 5;        // warp 0..15
        const int s  = (t >> 3) & 3;  // sample within warp
        const int e  = t & 7;         // quad within GC=32
        const float* inL_n = inL + (size_t)n * H_ * W_ * C_;
        #pragma unroll
        for (int k = 0; k < 8; ++k) {
            int S = k * 64 + wp * 4 + s;    // 0..511
            int g = S >> 5;
            int w = S & 31;
            ull w00 = spw[S];
            ull w10 = spw[S + 512];
            ull w01 = spw[S + 1024];
            ull w11 = spw[S + 1536];
            int4 ofs = spo[S];
            const float* bp = inL_n + g * 32 + e * 4;
            ulonglong2 a = *(const ulonglong2*)(bp + ofs.x);
            ulonglong2 b = *(const ulonglong2*)(bp + ofs.y);
            ulonglong2 c = *(const ulonglong2*)(bp + ofs.z);
            ulonglong2 d = *(const ulonglong2*)(bp + ofs.w);
            ull rlo = mul2(w00, a.x);
            rlo = fma2(w10, b.x, rlo);
            rlo = fma2(w01, c.x, rlo);
            rlo = fma2(w11, d.x, rlo);
            ull rhi = mul2(w00, a.y);
            rhi = fma2(w10, b.y, rhi);
            rhi = fma2(w01, c.y, rhi);
            rhi = fma2(w11, d.y, rhi);
            float r0, r1, r2, r3;
            unpack2(rlo, r0, r1);
            unpack2(rhi, r2, r3);
            int crow = g * 32 + e * 4;
            stage[(crow + 0) * 33 + w] = r0;
            stage[(crow + 1) * 33 + w] = r1;
            stage[(crow + 2) * 33 + w] = r2;
            stage[(crow + 3) * 33 + w] = r3;
        }
    }
    __syncthreads();

    // ======== Phase F: coalesced copy-out ====================================
    {
        float* outp = out + (size_t)n * C_ * H_ * W_ + (size_t)h * W_ + wbase;
        #pragma unroll
        for (int k = 0; k < 8; ++k) {
            int c = (t >> 3) + k * 64;
            float4 r;
            r.x = stage[c * 33 + w4 * 4 + 0];
            r.y = stage[c * 33 + w4 * 4 + 1];
            r.z = stage[c * 33 + w4 * 4 + 2];
            r.w = stage[c * 33 + w4 * 4 + 3];
            *(float4*)(outp + (size_t)c * (H_ * W_) + w4 * 4) = r;
        }
    }
}

extern "C" void kernel_launch(void* const* d_in, const int* in_sizes, int n_in,
                              void* d_out, int out_size)
{
    (void)in_sizes; (void)n_in; (void)out_size;
    const float* in0   = (const float*)d_in[0];
    const float* inL   = (const float*)d_in[1];
    const float* dw_w  = (const float*)d_in[2];
    const float* dw_b  = (const float*)d_in[3];
    const float* ln_g  = (const float*)d_in[4];
    const float* ln_b  = (const float*)d_in[5];
    const float* off_w = (const float*)d_in[6];
    const float* off_b = (const float*)d_in[7];
    float* out = (float*)d_out;

    const int smem_bytes = SMEM_FLOATS * sizeof(float);   // 106752
    cudaFuncSetAttribute(das_fused_kernel,
                         cudaFuncAttributeMaxDynamicSharedMemorySize, smem_bytes);

    dim3 grid(2, H_, N_);
    das_fused_kernel<<<grid, 512, smem_bytes>>>(in0, inL, dw_w, dw_b,
                                                ln_g, ln_b, off_w, off_b, out);
}

// round 17
// speedup vs baseline: 1.0976x; 1.0976x over previous
#include <cuda_runtime.h>
#include <math.h>

#define N_ 8
#define C_ 512
#define H_ 64
#define W_ 64

typedef unsigned long long ull;

__device__ __forceinline__ ull pack2(float lo, float hi) {
    ull r; asm("mov.b64 %0, {%1, %2};" : "=l"(r) : "f"(lo), "f"(hi)); return r;
}
__device__ __forceinline__ void unpack2(ull v, float& lo, float& hi) {
    asm("mov.b64 {%0, %1}, %2;" : "=f"(lo), "=f"(hi) : "l"(v));
}
__device__ __forceinline__ ull fma2(ull a, ull b, ull c) {
    ull d; asm("fma.rn.f32x2 %0, %1, %2, %3;" : "=l"(d) : "l"(a), "l"(b), "l"(c)); return d;
}
__device__ __forceinline__ ull mul2(ull a, ull b) {
    ull d; asm("mul.rn.f32x2 %0, %1, %2;" : "=l"(d) : "l"(a), "l"(b)); return d;
}
__device__ __forceinline__ float tanh_ap(float x) {
    float r; asm("tanh.approx.f32 %0, %1;" : "=f"(r) : "f"(x)); return r;
}
// tanh-form GELU on an f32x2 pair
__device__ __forceinline__ ull gelu2(ull y, ull C1, ull C0, ull HF) {
    ull x2 = mul2(y, y);
    ull u  = mul2(y, fma2(C1, x2, C0));
    float u0, u1;
    unpack2(u, u0, u1);
    ull t2 = pack2(tanh_ap(u0), tanh_ap(u1));
    ull r  = fma2(t2, HF, HF);
    return mul2(y, r);
}

// Shared memory (floats), per CTA of 512 threads covering 32 pixels:
//   region0 (18432): x1 [512 rows][36] A-D; after D: partials
//                    [8 parts][32 o, stride 36] = 9216;
//                    stage E/F: stride-32 rows, XOR swizzle
//                    addr = c*32 + (w ^ (((c>>2)&7)<<2))  (16384 floats)
//   offsP   (8192):  phase0-A: dwws [0:6144]; A/B: psum/psq [6144:7200]
//                    C-D: half of off_w^T, swizzled float4 slots [0:8192]
//                    E0/E: spw 4x512 ull [0:4096] + spo int4 [4096:6144]
//   mu,rs   : 64
// total = 26688 floats = 106752 B  -> 2 CTAs/SM
#define SMEM_FLOATS (18432 + 8192 + 64)

__global__ __launch_bounds__(512, 2)
void das_fused_kernel(const float* __restrict__ in0,   // input_first NCHW
                      const float* __restrict__ inL,   // input_last  NHWC
                      const float* __restrict__ dw_w,  // [C,1,3,3]
                      const float* __restrict__ dw_b,  // [C]
                      const float* __restrict__ ln_g,  // [C]
                      const float* __restrict__ ln_b,  // [C]
                      const float* __restrict__ off_w, // [2G, C]
                      const float* __restrict__ off_b, // [2G]
                      float* __restrict__ out)         // NCHW
{
    extern __shared__ float sm[];
    float* x1    = sm;                 // stride 36 rows (A-D)
    float* stage = sm;                 // stride 32 rows + swizzle (E-F)
    float* parts = sm;                 // [0:9216] after D (x1 dead)
    float* offsP = sm + 18432;         // 8192
    float* dwws  = offsP;              // [0:6144] staged dw weights
    float* psum  = offsP + 6144;       // 16 x 33 = 528
    float* psq   = offsP + 6672;       // 16 x 33 = 528
    float* wsm   = offsP;              // [0:8192] staged off_w half (C-D)
    ull*   spw   = (ull*)offsP;        // [0:4096] (E0/E)
    int4*  spo   = (int4*)(offsP + 4096);  // [4096:6144] tap offsets
    float* mu    = sm + 18432 + 8192;  // 32
    float* rs    = mu + 32;            // 32

    const int t     = threadIdx.x;
    const int half  = blockIdx.x;      // 0 or 1
    const int h     = blockIdx.y;
    const int n     = blockIdx.z;
    const int wbase = half * 32;

    const int w4   = t & 7;            // w-quad within the 32 pixels
    const int cgrp = t >> 3;           // 0..63, 8 channels each
    const int lane = t & 31;

    // ======== Phase 0: stage dw_w (9-stride) into dwws (12-stride) ==========
    {
        const float4* s4 = (const float4*)dw_w;   // 4608 floats = 1152 float4
        #pragma unroll
        for (int k = 0; k < 3; ++k) {
            int idx = t + k * 512;
            if (idx < 1152) {
                float4 v = __ldg(s4 + idx);
                float va[4] = {v.x, v.y, v.z, v.w};
                int j0 = idx * 4;
                #pragma unroll
                for (int e = 0; e < 4; ++e) {
                    int j = j0 + e;
                    int c = (int)(((unsigned)j * 7282u) >> 16);   // j / 9
                    int r = j - c * 9;
                    dwws[c * 12 + r] = va[e];
                }
            }
        }
    }
    __syncthreads();

    // ======== Phase A: depthwise 3x3 conv + bias + LN partials ==============
    float s0 = 0.f, s1 = 0.f, s2 = 0.f, s3 = 0.f;
    float q0 = 0.f, q1 = 0.f, q2 = 0.f, q3 = 0.f;

    const float* in_n = in0 + (size_t)n * C_ * H_ * W_;

    #pragma unroll 4
    for (int i = 0; i < 8; ++i) {
        int c = cgrp * 8 + i;
        const float4* wp4 = (const float4*)(dwws + c * 12);
        float4 wA = wp4[0];
        float4 wB = wp4[1];
        float4 wC = wp4[2];
        const float* cp = in_n + (size_t)c * H_ * W_;
        float b = __ldg(dw_b + c);
        float a0 = b, a1 = b, a2 = b, a3 = b;
        #pragma unroll
        for (int dy = -1; dy <= 1; ++dy) {
            int hy = h + dy;
            if ((unsigned)hy < (unsigned)H_) {          // uniform across block
                const float* r = cp + hy * W_ + wbase + w4 * 4;
                float4 v = *(const float4*)r;
                float lf = __shfl_up_sync(0xffffffffu, v.w, 1, 8);
                if (w4 == 0) lf = (wbase > 0) ? r[-1] : 0.f;
                float rt = __shfl_down_sync(0xffffffffu, v.x, 1, 8);
                if (w4 == 7) rt = (wbase + 32 < W_) ? r[4] : 0.f;
                float k0, k1, k2;
                if (dy == -1)     { k0 = wA.x; k1 = wA.y; k2 = wA.z; }
                else if (dy == 0) { k0 = wA.w; k1 = wB.x; k2 = wB.y; }
                else              { k0 = wB.z; k1 = wB.w; k2 = wC.x; }
                a0 += k0 * lf  + k1 * v.x + k2 * v.y;
                a1 += k0 * v.x + k1 * v.y + k2 * v.z;
                a2 += k0 * v.y + k1 * v.z + k2 * v.w;
                a3 += k0 * v.z + k1 * v.w + k2 * rt;
            }
        }
        s0 += a0; q0 += a0 * a0;
        s1 += a1; q1 += a1 * a1;
        s2 += a2; q2 += a2 * a2;
        s3 += a3; q3 += a3 * a3;
        *(float4*)(x1 + c * 36 + w4 * 4) = make_float4(a0, a1, a2, a3);
    }

    s0 += __shfl_xor_sync(0xffffffffu, s0, 8);
    s0 += __shfl_xor_sync(0xffffffffu, s0, 16);
    s1 += __shfl_xor_sync(0xffffffffu, s1, 8);
    s1 += __shfl_xor_sync(0xffffffffu, s1, 16);
    s2 += __shfl_xor_sync(0xffffffffu, s2, 8);
    s2 += __shfl_xor_sync(0xffffffffu, s2, 16);
    s3 += __shfl_xor_sync(0xffffffffu, s3, 8);
    s3 += __shfl_xor_sync(0xffffffffu, s3, 16);
    q0 += __shfl_xor_sync(0xffffffffu, q0, 8);
    q0 += __shfl_xor_sync(0xffffffffu, q0, 16);
    q1 += __shfl_xor_sync(0xffffffffu, q1, 8);
    q1 += __shfl_xor_sync(0xffffffffu, q1, 16);
    q2 += __shfl_xor_sync(0xffffffffu, q2, 8);
    q2 += __shfl_xor_sync(0xffffffffu, q2, 16);
    q3 += __shfl_xor_sync(0xffffffffu, q3, 8);
    q3 += __shfl_xor_sync(0xffffffffu, q3, 16);
    {
        int warpId = t >> 5;               // 0..15
        if (lane < 8) {
            psum[warpId * 33 + lane * 4 + 0] = s0;
            psum[warpId * 33 + lane * 4 + 1] = s1;
            psum[warpId * 33 + lane * 4 + 2] = s2;
            psum[warpId * 33 + lane * 4 + 3] = s3;
            psq [warpId * 33 + lane * 4 + 0] = q0;
            psq [warpId * 33 + lane * 4 + 1] = q1;
            psq [warpId * 33 + lane * 4 + 2] = q2;
            psq [warpId * 33 + lane * 4 + 3] = q3;
        }
    }
    __syncthreads();

    // ======== Phase B: finish LN statistics, all threads + shfl =============
    {
        int px = t >> 4;      // 0..31
        int j  = t & 15;      // partial index
        float s = psum[j * 33 + px];
        float q = psq [j * 33 + px];
        #pragma unroll
        for (int d = 8; d >= 1; d >>= 1) {
            s += __shfl_xor_sync(0xffffffffu, s, d);
            q += __shfl_xor_sync(0xffffffffu, q, d);
        }
        if (j == 0) {
            float m = s * (1.0f / 512.0f);
            float var = q * (1.0f / 512.0f) - m * m;
            mu[px] = m;
            rs[px] = rsqrtf(var + 1e-6f);
        }
    }
    __syncthreads();

    // ======== Phase C: LN + fast GELU, in place; stage weight half 0 ========
    {
        // stage off_w^T for c in [0,256): thread t -> c = t>>1, o-block (t&1)
        // swizzled float4 slot: c*8 + (og ^ (c & 7))
        {
            int c  = t >> 1;
            int ob = (t & 1) * 16;          // o base (16 o's per thread)
            #pragma unroll
            for (int s = 0; s < 4; ++s) {
                int og = (ob >> 2) + s;
                float4 wv;
                wv.x = __ldg(off_w + (ob + s * 4 + 0) * 512 + c);
                wv.y = __ldg(off_w + (ob + s * 4 + 1) * 512 + c);
                wv.z = __ldg(off_w + (ob + s * 4 + 2) * 512 + c);
                wv.w = __ldg(off_w + (ob + s * 4 + 3) * 512 + c);
                ((float4*)wsm)[c * 8 + (og ^ (c & 7))] = wv;
            }
        }

        float4 m4 = *(const float4*)(mu + w4 * 4);
        float4 r4 = *(const float4*)(rs + w4 * 4);
        const ull C1 = pack2(0.0356774081f, 0.0356774081f);
        const ull C0 = pack2(0.7978845608f, 0.7978845608f);
        const ull HF = pack2(0.5f, 0.5f);
        ull r2lo = pack2(r4.x, r4.y);
        ull r2hi = pack2(r4.z, r4.w);
        ull mn2lo = pack2(-m4.x, -m4.y);
        ull mn2hi = pack2(-m4.z, -m4.w);
        #pragma unroll
        for (int q = 0; q < 2; ++q) {
            int c0 = cgrp * 8 + q * 4;
            float4 gq = __ldg((const float4*)(ln_g + c0));
            float4 bq = __ldg((const float4*)(ln_b + c0));
            float gga[4] = {gq.x, gq.y, gq.z, gq.w};
            float bba[4] = {bq.x, bq.y, bq.z, bq.w};
            #pragma unroll
            for (int j = 0; j < 4; ++j) {
                int c = c0 + j;
                ull g2 = pack2(gga[j], gga[j]);
                ull b2 = pack2(bba[j], bba[j]);
                ulonglong2 yv = *(const ulonglong2*)(x1 + c * 36 + w4 * 4);
                ull Alo = mul2(r2lo, g2);
                ull Blo = fma2(mn2lo, Alo, b2);
                ull Ahi = mul2(r2hi, g2);
                ull Bhi = fma2(mn2hi, Ahi, b2);
                yv.x = fma2(yv.x, Alo, Blo);
                yv.y = fma2(yv.y, Ahi, Bhi);
                yv.x = gelu2(yv.x, C1, C0, HF);
                yv.y = gelu2(yv.y, C1, C0, HF);
                *(ulonglong2*)(x1 + c * 36 + w4 * 4) = yv;
            }
        }
    }
    __syncthreads();

    // ======== Phase D: offset projection, all-LDS weights, 2 passes =========
    {
        const int g4   = t & 7;          // w-quad
        const int og   = (t >> 3) & 7;   // o-quad
        const int part = t >> 6;         // c-part, 32 channels / pass
        ull a00 = 0, a01 = 0, a10 = 0, a11 = 0;
        ull a20 = 0, a21 = 0, a30 = 0, a31 = 0;
        #pragma unroll
        for (int pass = 0; pass < 2; ++pass) {
            if (pass == 1) {
                __syncthreads();     // pass-0 weight reads complete
                int c  = 256 + (t >> 1);
                int ob = (t & 1) * 16;
                #pragma unroll
                for (int s = 0; s < 4; ++s) {
                    int og2 = (ob >> 2) + s;
                    float4 wv;
                    wv.x = __ldg(off_w + (ob + s * 4 + 0) * 512 + c);
                    wv.y = __ldg(off_w + (ob + s * 4 + 1) * 512 + c);
                    wv.z = __ldg(off_w + (ob + s * 4 + 2) * 512 + c);
                    wv.w = __ldg(off_w + (ob + s * 4 + 3) * 512 + c);
                    ((float4*)wsm)[(c - 256) * 8 + (og2 ^ (c & 7))] = wv;
                }
                __syncthreads();     // half-1 staged
            }
            int cb = pass * 256 + part * 32;
            #pragma unroll 4
            for (int ci = 0; ci < 32; ++ci) {
                int c  = cb + ci;
                int cl = c - pass * 256;
                ulonglong2 xv = *(const ulonglong2*)(x1 + c * 36 + g4 * 4);
                float4 wv = ((const float4*)wsm)[cl * 8 + (og ^ (cl & 7))];
                ull w0 = pack2(wv.x, wv.x);
                ull w1 = pack2(wv.y, wv.y);
                ull w2 = pack2(wv.z, wv.z);
                ull w3 = pack2(wv.w, wv.w);
                a00 = fma2(w0, xv.x, a00); a01 = fma2(w0, xv.y, a01);
                a10 = fma2(w1, xv.x, a10); a11 = fma2(w1, xv.y, a11);
                a20 = fma2(w2, xv.x, a20); a21 = fma2(w2, xv.y, a21);
                a30 = fma2(w3, xv.x, a30); a31 = fma2(w3, xv.y, a31);
            }
        }
        __syncthreads();   // all x1 + wsm reads complete
        float* pp = parts + part * 1152 + og * 144 + g4 * 4;   // o-stride 36
        ((ull*)(pp +   0))[0] = a00; ((ull*)(pp +   0))[1] = a01;
        ((ull*)(pp +  36))[0] = a10; ((ull*)(pp +  36))[1] = a11;
        ((ull*)(pp +  72))[0] = a20; ((ull*)(pp +  72))[1] = a21;
        ((ull*)(pp + 108))[0] = a30; ((ull*)(pp + 108))[1] = a31;
    }
    __syncthreads();

    // ======== Phase E0: reduce partials + per-sample bilinear params =========
    {
        const int S = t;            // 0..511
        const int g = S >> 5;
        const int w = S & 31;
        float sx = __ldg(off_b + 2 * g);
        float sy = __ldg(off_b + 2 * g + 1);
        #pragma unroll
        for (int p = 0; p < 8; ++p) {
            sx += parts[p * 1152 + g * 72 + w];          // o = 2g
            sy += parts[p * 1152 + g * 72 + 36 + w];     // o = 2g+1
        }
        float px = (float)(wbase + w) + sx;
        float py = (float)h           + sy;
        float x0f = floorf(px);
        float y0f = floorf(py);
        float fx = px - x0f;
        float fy = py - y0f;
        int x0 = (int)x0f;
        int y0 = (int)y0f;
        float vx0 = (x0f >= 0.f       && x0f <= 63.f)       ? 1.f : 0.f;
        float vx1 = (x0f + 1.f >= 0.f && x0f + 1.f <= 63.f) ? 1.f : 0.f;
        float vy0 = (y0f >= 0.f       && y0f <= 63.f)       ? 1.f : 0.f;
        float vy1 = (y0f + 1.f >= 0.f && y0f + 1.f <= 63.f) ? 1.f : 0.f;
        int xc0 = min(max(x0, 0), 63);
        int xc1 = min(max(x0 + 1, 0), 63);
        int yc0 = min(max(y0, 0), 63);
        int yc1 = min(max(y0 + 1, 0), 63);
        float w00 = (1.f - fx) * (1.f - fy) * vx0 * vy0;
        float w10 = fx * (1.f - fy) * vx1 * vy0;
        float w01 = (1.f - fx) * fy * vx0 * vy1;
        float w11 = fx * fy * vx1 * vy1;
        spw[S +    0] = pack2(w00, w00);
        spw[S +  512] = pack2(w10, w10);
        spw[S + 1024] = pack2(w01, w01);
        spw[S + 1536] = pack2(w11, w11);
        spo[S] = make_int4((yc0 * 64 + xc0) * 512, (yc0 * 64 + xc1) * 512,
                           (yc1 * 64 + xc0) * 512, (yc1 * 64 + xc1) * 512);
    }
    __syncthreads();

    // ======== Phase E: coalesced bilinear gather (8 lanes per sample) =======
    {
        const int wp = t >> 5;        // warp 0..15
        const int s  = (t >> 3) & 3;  // sample within warp
        const int e  = t & 7;         // quad within GC=32
        const int esw = e << 2;       // stage swizzle for this thread's rows
        const float* inL_n = inL + (size_t)n * H_ * W_ * C_;
        #pragma unroll
        for (int k = 0; k < 8; ++k) {
            int S = k * 64 + wp * 4 + s;    // 0..511
            int g = S >> 5;
            int w = S & 31;
            ull w00 = spw[S];
            ull w10 = spw[S + 512];
            ull w01 = spw[S + 1024];
            ull w11 = spw[S + 1536];
            int4 ofs = spo[S];
            const float* bp = inL_n + g * 32 + e * 4;
            ulonglong2 a = *(const ulonglong2*)(bp + ofs.x);
            ulonglong2 b = *(const ulonglong2*)(bp + ofs.y);
            ulonglong2 c = *(const ulonglong2*)(bp + ofs.z);
            ulonglong2 d = *(const ulonglong2*)(bp + ofs.w);
            ull rlo = mul2(w00, a.x);
            rlo = fma2(w10, b.x, rlo);
            rlo = fma2(w01, c.x, rlo);
            rlo = fma2(w11, d.x, rlo);
            ull rhi = mul2(w00, a.y);
            rhi = fma2(w10, b.y, rhi);
            rhi = fma2(w01, c.y, rhi);
            rhi = fma2(w11, d.y, rhi);
            float r0, r1, r2, r3;
            unpack2(rlo, r0, r1);
            unpack2(rhi, r2, r3);
            int crow = g * 32 + e * 4;
            int ws = w ^ esw;       // swizzled column: conflict-free STS
            stage[(crow + 0) * 32 + ws] = r0;
            stage[(crow + 1) * 32 + ws] = r1;
            stage[(crow + 2) * 32 + ws] = r2;
            stage[(crow + 3) * 32 + ws] = r3;
        }
    }
    __syncthreads();

    // ======== Phase F: copy-out, LDS.128 from swizzled stage =================
    {
        float* outp = out + (size_t)n * C_ * H_ * W_ + (size_t)h * W_ + wbase;
        #pragma unroll
        for (int k = 0; k < 8; ++k) {
            int c = (t >> 3) + k * 64;
            int sw = (w4 * 4) ^ (((c >> 2) & 7) << 2);
            float4 r = *(const float4*)(stage + c * 32 + sw);
            *(float4*)(outp + (size_t)c * (H_ * W_) + w4 * 4) = r;
        }
    }
}

extern "C" void kernel_launch(void* const* d_in, const int* in_sizes, int n_in,
                              void* d_out, int out_size)
{
    (void)in_sizes; (void)n_in; (void)out_size;
    const float* in0   = (const float*)d_in[0];
    const float* inL   = (const float*)d_in[1];
    const float* dw_w  = (const float*)d_in[2];
    const float* dw_b  = (const float*)d_in[3];
    const float* ln_g  = (const float*)d_in[4];
    const float* ln_b  = (const float*)d_in[5];
    const float* off_w = (const float*)d_in[6];
    const float* off_b = (const float*)d_in[7];
    float* out = (float*)d_out;

    const int smem_bytes = SMEM_FLOATS * sizeof(float);   // 106752
    cudaFuncSetAttribute(das_fused_kernel,
                         cudaFuncAttributeMaxDynamicSharedMemorySize, smem_bytes);

    dim3 grid(2, H_, N_);
    das_fused_kernel<<<grid, 512, smem_bytes>>>(in0, inL, dw_w, dw_b,
                                                ln_g, ln_b, off_w, off_b, out);
}